// round 1
// baseline (speedup 1.0000x reference)
#include <cuda_runtime.h>
#include <cstdint>

// Problem constants (fixed by the dataset)
#define NN   30000
#define EE   480000
#define ET   (EE + NN)      // edges + self loops
#define INF_ 256
#define OUTF 128
#define HH   4
#define HC   (HH * OUTF)    // 512
#define NEG_SLOPE 0.2f

// ---------------- device scratch (no allocs allowed) ----------------
__device__ float    g_h[(size_t)NN * HC];     // projected features [N, H*C]  (61.4 MB)
__device__ float    g_as[NN * HH];            // per-node src attention logits
__device__ float    g_ad[NN * HH];            // per-node dst attention logits
__device__ unsigned g_amax[NN * HH];          // segment max (ordered-uint encoded)
__device__ float    g_denom[NN * HH];         // segment softmax denominator

// ordered-uint encoding so atomicMax works on signed floats
__device__ __forceinline__ unsigned fenc(float f) {
    unsigned u = __float_as_uint(f);
    return (u & 0x80000000u) ? ~u : (u | 0x80000000u);
}
__device__ __forceinline__ float fdec(unsigned e) {
    e = (e & 0x80000000u) ? (e ^ 0x80000000u) : ~e;
    return __uint_as_float(e);
}
__device__ __forceinline__ float lrelu(float f) {
    return f > 0.0f ? f : NEG_SLOPE * f;
}

// ---------------- 1) GEMM: h = x @ W   [30000,256]x[256,512] ----------------
// Classic 128x128x8 SMEM-tiled SGEMM, 256 threads, 8x8 microtile.
__global__ void __launch_bounds__(256) gemm_kernel(const float* __restrict__ x,
                                                   const float* __restrict__ W) {
    __shared__ __align__(16) float As[8][128];
    __shared__ __align__(16) float Bs[8][128];

    const int bm = blockIdx.y * 128;
    const int bn = blockIdx.x * 128;
    const int tid = threadIdx.x;
    const int tx = tid % 16;          // 0..15 -> 8 cols each
    const int ty = tid / 16;          // 0..15 -> 8 rows each

    const int loadArow = tid >> 1;            // 0..127
    const int loadAk   = (tid & 1) * 4;       // 0 or 4
    const int loadBk   = tid >> 5;            // 0..7
    const int loadBn   = (tid & 31) * 4;      // 0..124

    float acc[8][8];
#pragma unroll
    for (int i = 0; i < 8; i++)
#pragma unroll
        for (int j = 0; j < 8; j++) acc[i][j] = 0.0f;

    for (int k0 = 0; k0 < INF_; k0 += 8) {
        const int grow = bm + loadArow;
        float4 av = make_float4(0.f, 0.f, 0.f, 0.f);
        if (grow < NN)
            av = *(const float4*)&x[(size_t)grow * INF_ + k0 + loadAk];
        As[loadAk + 0][loadArow] = av.x;
        As[loadAk + 1][loadArow] = av.y;
        As[loadAk + 2][loadArow] = av.z;
        As[loadAk + 3][loadArow] = av.w;

        float4 bv = *(const float4*)&W[(size_t)(k0 + loadBk) * HC + bn + loadBn];
        *(float4*)&Bs[loadBk][loadBn] = bv;
        __syncthreads();

#pragma unroll
        for (int kk = 0; kk < 8; kk++) {
            float a[8], b[8];
            *(float4*)&a[0] = *(const float4*)&As[kk][ty * 8];
            *(float4*)&a[4] = *(const float4*)&As[kk][ty * 8 + 4];
            *(float4*)&b[0] = *(const float4*)&Bs[kk][tx * 8];
            *(float4*)&b[4] = *(const float4*)&Bs[kk][tx * 8 + 4];
#pragma unroll
            for (int i = 0; i < 8; i++)
#pragma unroll
                for (int j = 0; j < 8; j++) acc[i][j] += a[i] * b[j];
        }
        __syncthreads();
    }

#pragma unroll
    for (int i = 0; i < 8; i++) {
        const int row = bm + ty * 8 + i;
        if (row < NN) {
            float* dst = &g_h[(size_t)row * HC + bn + tx * 8];
            *(float4*)&dst[0] = make_float4(acc[i][0], acc[i][1], acc[i][2], acc[i][3]);
            *(float4*)&dst[4] = make_float4(acc[i][4], acc[i][5], acc[i][6], acc[i][7]);
        }
    }
}

// ---------------- 2) per-node attention dots  a_s, a_d [N,H] ----------------
// One block per node; warp w handles head w.
__global__ void __launch_bounds__(128) attn_dot_kernel(const float* __restrict__ att_src,
                                                       const float* __restrict__ att_dst) {
    const int n    = blockIdx.x;
    const int head = threadIdx.x >> 5;
    const int lane = threadIdx.x & 31;

    float s1 = 0.f, s2 = 0.f;
    const float* hp = &g_h[(size_t)n * HC + head * OUTF];
#pragma unroll
    for (int c0 = 0; c0 < OUTF; c0 += 32) {
        const float hv = hp[c0 + lane];
        s1 += hv * att_src[head * OUTF + c0 + lane];
        s2 += hv * att_dst[head * OUTF + c0 + lane];
    }
#pragma unroll
    for (int o = 16; o > 0; o >>= 1) {
        s1 += __shfl_down_sync(0xFFFFFFFFu, s1, o);
        s2 += __shfl_down_sync(0xFFFFFFFFu, s2, o);
    }
    if (lane == 0) {
        g_as[n * HH + head] = s1;
        g_ad[n * HH + head] = s2;
    }
}

// ---------------- 3) init: zero out accumulator / amax / denom --------------
__global__ void init_kernel(float* __restrict__ out) {
    const int i = blockIdx.x * blockDim.x + threadIdx.x;
    const int total = NN * OUTF;            // 3,840,000
    for (int idx = i; idx < total; idx += gridDim.x * blockDim.x)
        out[idx] = 0.0f;
    if (i < NN * HH) {
        g_amax[i]  = 0u;                    // encodes below enc(-inf)
        g_denom[i] = 0.0f;
    }
}

// ---------------- 4) pass A: segment max over dst -------------------------
__global__ void __launch_bounds__(256) edge_max_kernel(const int* __restrict__ src,
                                                       const int* __restrict__ dst) {
    const int e = blockIdx.x * blockDim.x + threadIdx.x;
    if (e >= ET) return;
    int s, d;
    if (e < EE) { s = src[e]; d = dst[e]; } else { s = d = e - EE; }
    const float4 as4 = *(const float4*)&g_as[s * HH];
    const float4 ad4 = *(const float4*)&g_ad[d * HH];
    atomicMax(&g_amax[d * HH + 0], fenc(lrelu(as4.x + ad4.x)));
    atomicMax(&g_amax[d * HH + 1], fenc(lrelu(as4.y + ad4.y)));
    atomicMax(&g_amax[d * HH + 2], fenc(lrelu(as4.z + ad4.z)));
    atomicMax(&g_amax[d * HH + 3], fenc(lrelu(as4.w + ad4.w)));
}

// ---------------- 5) pass B: softmax denominator --------------------------
__global__ void __launch_bounds__(256) edge_denom_kernel(const int* __restrict__ src,
                                                         const int* __restrict__ dst) {
    const int e = blockIdx.x * blockDim.x + threadIdx.x;
    if (e >= ET) return;
    int s, d;
    if (e < EE) { s = src[e]; d = dst[e]; } else { s = d = e - EE; }
    const float4 as4 = *(const float4*)&g_as[s * HH];
    const float4 ad4 = *(const float4*)&g_ad[d * HH];
    const float a0 = lrelu(as4.x + ad4.x), a1 = lrelu(as4.y + ad4.y);
    const float a2 = lrelu(as4.z + ad4.z), a3 = lrelu(as4.w + ad4.w);
    atomicAdd(&g_denom[d * HH + 0], __expf(a0 - fdec(g_amax[d * HH + 0])));
    atomicAdd(&g_denom[d * HH + 1], __expf(a1 - fdec(g_amax[d * HH + 1])));
    atomicAdd(&g_denom[d * HH + 2], __expf(a2 - fdec(g_amax[d * HH + 2])));
    atomicAdd(&g_denom[d * HH + 3], __expf(a3 - fdec(g_amax[d * HH + 3])));
}

// ---------------- 6) pass C: weighted scatter, heads folded ---------------
// One warp per edge. Lanes 0..3 compute w[h]; all lanes gather 16 channels
// of h[src] and atomicAdd the head-combined message into out[dst, :128].
// 1/H is folded in here so no separate head-mean pass is needed.
__global__ void __launch_bounds__(256) edge_scatter_kernel(const int* __restrict__ src,
                                                           const int* __restrict__ dst,
                                                           float* __restrict__ out) {
    const int gw   = (blockIdx.x * blockDim.x + threadIdx.x) >> 5;
    const int lane = threadIdx.x & 31;
    if (gw >= ET) return;
    int s, d;
    if (gw < EE) { s = src[gw]; d = dst[gw]; } else { s = d = gw - EE; }

    float w = 0.0f;
    if (lane < HH) {
        const float al = lrelu(g_as[s * HH + lane] + g_ad[d * HH + lane]);
        const float ex = __expf(al - fdec(g_amax[d * HH + lane]));
        w = ex / g_denom[d * HH + lane] * 0.25f;   // fold 1/H
    }
    const float w0 = __shfl_sync(0xFFFFFFFFu, w, 0);
    const float w1 = __shfl_sync(0xFFFFFFFFu, w, 1);
    const float w2 = __shfl_sync(0xFFFFFFFFu, w, 2);
    const float w3 = __shfl_sync(0xFFFFFFFFu, w, 3);

    const float* hs = &g_h[(size_t)s * HC];
    float* od = &out[(size_t)d * OUTF];
#pragma unroll
    for (int c0 = 0; c0 < OUTF; c0 += 32) {
        const int c = c0 + lane;
        const float v = w0 * hs[c] + w1 * hs[OUTF + c] +
                        w2 * hs[2 * OUTF + c] + w3 * hs[3 * OUTF + c];
        atomicAdd(&od[c], v);
    }
}

// ---------------- 7) epilogue: bias + tanh --------------------------------
__global__ void finish_kernel(float* __restrict__ out, const float* __restrict__ bias) {
    const int i = blockIdx.x * blockDim.x + threadIdx.x;
    const int total = NN * OUTF;
    for (int idx = i; idx < total; idx += gridDim.x * blockDim.x)
        out[idx] = tanhf(out[idx] + bias[idx & (OUTF - 1)]);
}

// ---------------- launch ---------------------------------------------------
extern "C" void kernel_launch(void* const* d_in, const int* in_sizes, int n_in,
                              void* d_out, int out_size) {
    const float* x        = (const float*)d_in[0];
    const int*   eidx     = (const int*)  d_in[1];   // [2, E]
    const float* W        = (const float*)d_in[2];
    const float* att_src  = (const float*)d_in[3];
    const float* att_dst  = (const float*)d_in[4];
    const float* bias     = (const float*)d_in[5];
    float*       out      = (float*)d_out;

    const int* src = eidx;
    const int* dst = eidx + EE;

    // 1) projection GEMM
    {
        dim3 grid(HC / 128, (NN + 127) / 128);   // (4, 235)
        gemm_kernel<<<grid, 256>>>(x, W);
    }
    // 2) per-node attention dots
    attn_dot_kernel<<<NN, 128>>>(att_src, att_dst);
    // 3) init accumulators
    init_kernel<<<(NN * OUTF + 255) / 256, 256>>>(out);
    // 4) segment max
    edge_max_kernel<<<(ET + 255) / 256, 256>>>(src, dst);
    // 5) softmax denom
    edge_denom_kernel<<<(ET + 255) / 256, 256>>>(src, dst);
    // 6) weighted scatter (warp per edge)
    edge_scatter_kernel<<<(ET + 7) / 8, 256>>>(src, dst, out);
    // 7) bias + tanh
    finish_kernel<<<(NN * OUTF + 255) / 256, 256>>>(out, bias);
}

// round 3
// speedup vs baseline: 2.1452x; 2.1452x over previous
#include <cuda_runtime.h>
#include <cuda_bf16.h>
#include <cstdint>

// Problem constants
#define NN   30000
#define EE   480000
#define ET   (EE + NN)
#define INF_ 256
#define OUTF 128
#define HH   4
#define HC   (HH * OUTF)      // 512
#define NEG_SLOPE 0.2f

// ---------------- device scratch ----------------
__device__ float          g_h[(size_t)NN * HC];        // projected features (61.4 MB)
__device__ float          g_as[NN * HH];
__device__ float          g_ad[NN * HH];
__device__ __nv_bfloat16  g_x_hi[(size_t)NN * INF_];   // x split (15.4 MB each)
__device__ __nv_bfloat16  g_x_lo[(size_t)NN * INF_];
__device__ __nv_bfloat16  g_Wt_hi[HC * INF_];          // W^T split [512][256]
__device__ __nv_bfloat16  g_Wt_lo[HC * INF_];
__device__ int            g_deg[NN];
__device__ int            g_off[NN + 1];
__device__ int            g_pos[NN];
__device__ int            g_bin[ET];                   // CSR src ids grouped by dst

__device__ __forceinline__ float lrelu(float f) { return f > 0.0f ? f : NEG_SLOPE * f; }

__device__ __forceinline__ uint32_t smem_u32(const void* p) {
    uint32_t a;
    asm("{ .reg .u64 t; cvta.to.shared.u64 t, %1; cvt.u32.u64 %0, t; }" : "=r"(a) : "l"(p));
    return a;
}
__device__ __forceinline__ void ldsm4(uint32_t* r, uint32_t addr) {
    asm volatile("ldmatrix.sync.aligned.m8n8.x4.shared.b16 {%0,%1,%2,%3}, [%4];"
                 : "=r"(r[0]), "=r"(r[1]), "=r"(r[2]), "=r"(r[3]) : "r"(addr));
}
__device__ __forceinline__ void mma_bf16(float* c, const uint32_t* a, const uint32_t* b) {
    asm volatile(
        "mma.sync.aligned.m16n8k16.row.col.f32.bf16.bf16.f32 "
        "{%0,%1,%2,%3}, {%4,%5,%6,%7}, {%8,%9}, {%0,%1,%2,%3};"
        : "+f"(c[0]), "+f"(c[1]), "+f"(c[2]), "+f"(c[3])
        : "r"(a[0]), "r"(a[1]), "r"(a[2]), "r"(a[3]), "r"(b[0]), "r"(b[1]));
}

// ---------------- 0) prep: split x and W^T into bf16 hi/lo; zero accumulators ----
__global__ void prep_kernel(const float* __restrict__ x, const float* __restrict__ W) {
    const int idx = blockIdx.x * blockDim.x + threadIdx.x;
    if (idx < NN * INF_) {
        const float v = x[idx];
        const __nv_bfloat16 hi = __float2bfloat16_rn(v);
        g_x_hi[idx] = hi;
        g_x_lo[idx] = __float2bfloat16_rn(v - __bfloat162float(hi));
    }
    if (idx < HC * INF_) {
        const int n = idx >> 8;          // 0..511
        const int k = idx & 255;
        const float v = W[(size_t)k * HC + n];
        const __nv_bfloat16 hi = __float2bfloat16_rn(v);
        g_Wt_hi[idx] = hi;
        g_Wt_lo[idx] = __float2bfloat16_rn(v - __bfloat162float(hi));
    }
    if (idx < NN * HH) { g_as[idx] = 0.0f; g_ad[idx] = 0.0f; }
    if (idx < NN) g_deg[idx] = 0;
}

// ---------------- 1) GEMM via mma.sync bf16 (hi/lo split) + fused attn dots -------
// Block 128(M) x 128(N), 256 threads = 8 warps (warp grid 4x2, warp tile 32x64).
// N-block == one head (128 cols).
__global__ void __launch_bounds__(256) gemm_mma_kernel(const float* __restrict__ att_src,
                                                       const float* __restrict__ att_dst) {
    __shared__ __align__(16) __nv_bfloat16 As[128][40];   // 32 used + 8 pad
    __shared__ __align__(16) __nv_bfloat16 Bs[128][40];   // B as [N][K]

    const int tid    = threadIdx.x;
    const int lane   = tid & 31;
    const int wid    = tid >> 5;
    const int warp_m = wid & 3;         // 4 warps in M
    const int warp_n = wid >> 2;        // 2 warps in N
    const int bm     = blockIdx.x * 128;
    const int n0     = blockIdx.y * 128;
    const int head   = blockIdx.y;

    float acc[2][8][4];
#pragma unroll
    for (int i = 0; i < 2; i++)
#pragma unroll
        for (int j = 0; j < 8; j++)
#pragma unroll
            for (int k = 0; k < 4; k++) acc[i][j][k] = 0.0f;

    // precompute ldmatrix smem addresses (constant across chunks except ks col)
    const uint32_t as_base = smem_u32(&As[0][0]);
    const uint32_t bs_base = smem_u32(&Bs[0][0]);
    // A: rows warp_m*32 + mt*16 + (lane%16), col (lane/16)*8 (+ks*16)
    const int a_row = warp_m * 32 + (lane & 15);
    const int a_col = (lane >> 4) * 8;
    // B: rows warp_n*64 + p*16 + (lane%8) + (lane/16)*8, col ((lane>>3)&1)*8 (+ks*16)
    const int b_row = warp_n * 64 + (lane & 7) + (lane >> 4) * 8;
    const int b_col = ((lane >> 3) & 1) * 8;

#pragma unroll 1
    for (int term = 0; term < 3; term++) {
        const __nv_bfloat16* __restrict__ Asrc = (term == 2) ? g_x_lo : g_x_hi;
        const __nv_bfloat16* __restrict__ Bsrc = (term == 1) ? g_Wt_lo : g_Wt_hi;
#pragma unroll 1
        for (int k0 = 0; k0 < INF_; k0 += 32) {
            // load A [128x32] and B [128x32] (B rows = N)
#pragma unroll
            for (int i = 0; i < 2; i++) {
                const int idx = tid + i * 256;        // 0..511 uint4
                const int row = idx >> 2;
                const int seg = (idx & 3) * 8;
                const int gr  = bm + row;
                uint4 av = make_uint4(0u, 0u, 0u, 0u);
                if (gr < NN)
                    av = *(const uint4*)&Asrc[(size_t)gr * INF_ + k0 + seg];
                *(uint4*)&As[row][seg] = av;
                *(uint4*)&Bs[row][seg] =
                    *(const uint4*)&Bsrc[(size_t)(n0 + row) * INF_ + k0 + seg];
            }
            __syncthreads();

#pragma unroll
            for (int ks = 0; ks < 2; ks++) {
                uint32_t af[2][4];
#pragma unroll
                for (int mt = 0; mt < 2; mt++) {
                    const uint32_t addr = as_base +
                        ((a_row + mt * 16) * 40 + ks * 16 + a_col) * 2;
                    ldsm4(af[mt], addr);
                }
#pragma unroll
                for (int p = 0; p < 4; p++) {
                    uint32_t bf[4];
                    const uint32_t addr = bs_base +
                        ((b_row + p * 16) * 40 + ks * 16 + b_col) * 2;
                    ldsm4(bf, addr);
#pragma unroll
                    for (int mt = 0; mt < 2; mt++) {
                        mma_bf16(acc[mt][2 * p],     af[mt], bf);
                        mma_bf16(acc[mt][2 * p + 1], af[mt], bf + 2);
                    }
                }
            }
            __syncthreads();
        }
    }

    // ---- epilogue: store g_h, fused attention dot partials ----
    const int r0 = lane >> 2;
    const int cq = (lane & 3) * 2;
    float da[2][2] = {{0.f, 0.f}, {0.f, 0.f}};   // [mt][half] dot with att_src
    float db[2][2] = {{0.f, 0.f}, {0.f, 0.f}};   // dot with att_dst

#pragma unroll
    for (int mt = 0; mt < 2; mt++) {
        const int gm0 = bm + warp_m * 32 + mt * 16 + r0;
        const int gm1 = gm0 + 8;
#pragma unroll
        for (int nt = 0; nt < 8; nt++) {
            const int cih = warp_n * 64 + nt * 8 + cq;     // col within head
            const int gc  = n0 + cih;
            const float s0 = att_src[head * OUTF + cih];
            const float s1 = att_src[head * OUTF + cih + 1];
            const float d0 = att_dst[head * OUTF + cih];
            const float d1 = att_dst[head * OUTF + cih + 1];
            const float c0 = acc[mt][nt][0], c1 = acc[mt][nt][1];
            const float c2 = acc[mt][nt][2], c3 = acc[mt][nt][3];
            da[mt][0] += c0 * s0 + c1 * s1;
            db[mt][0] += c0 * d0 + c1 * d1;
            da[mt][1] += c2 * s0 + c3 * s1;
            db[mt][1] += c2 * d0 + c3 * d1;
            if (gm0 < NN) *(float2*)&g_h[(size_t)gm0 * HC + gc] = make_float2(c0, c1);
            if (gm1 < NN) *(float2*)&g_h[(size_t)gm1 * HC + gc] = make_float2(c2, c3);
        }
    }
    // quad reduce (lanes sharing the same row differ only in bits 0-1 of lane)
#pragma unroll
    for (int mt = 0; mt < 2; mt++)
#pragma unroll
        for (int h = 0; h < 2; h++) {
            da[mt][h] += __shfl_xor_sync(0xFFFFFFFFu, da[mt][h], 1);
            da[mt][h] += __shfl_xor_sync(0xFFFFFFFFu, da[mt][h], 2);
            db[mt][h] += __shfl_xor_sync(0xFFFFFFFFu, db[mt][h], 1);
            db[mt][h] += __shfl_xor_sync(0xFFFFFFFFu, db[mt][h], 2);
        }
    if ((lane & 3) == 0) {
#pragma unroll
        for (int mt = 0; mt < 2; mt++)
#pragma unroll
            for (int h = 0; h < 2; h++) {
                const int gm = bm + warp_m * 32 + mt * 16 + r0 + h * 8;
                if (gm < NN) {
                    atomicAdd(&g_as[gm * HH + head], da[mt][h]);
                    atomicAdd(&g_ad[gm * HH + head], db[mt][h]);
                }
            }
    }
}

// ---------------- 2) CSR build ----------------
__global__ void hist_kernel(const int* __restrict__ dst) {
    const int e = blockIdx.x * blockDim.x + threadIdx.x;
    if (e >= ET) return;
    const int d = (e < EE) ? dst[e] : (e - EE);
    atomicAdd(&g_deg[d], 1);
}

__global__ void __launch_bounds__(1024) scan_kernel() {
    __shared__ int sm[1024];
    const int t = threadIdx.x;
    const int base = t * 30;
    int sum = 0;
#pragma unroll 1
    for (int i = 0; i < 30; i++) { const int j = base + i; if (j < NN) sum += g_deg[j]; }
    sm[t] = sum;
    __syncthreads();
    for (int s = 1; s < 1024; s <<= 1) {
        const int v = (t >= s) ? sm[t - s] : 0;
        __syncthreads();
        sm[t] += v;
        __syncthreads();
    }
    int run = sm[t] - sum;   // exclusive prefix
#pragma unroll 1
    for (int i = 0; i < 30; i++) {
        const int j = base + i;
        if (j < NN) { g_off[j] = run; g_pos[j] = run; run += g_deg[j]; }
    }
    if (t == 1023) g_off[NN] = ET;
}

__global__ void fill_kernel(const int* __restrict__ src, const int* __restrict__ dst) {
    const int e = blockIdx.x * blockDim.x + threadIdx.x;
    if (e >= ET) return;
    int s, d;
    if (e < EE) { s = src[e]; d = dst[e]; } else { s = d = e - EE; }
    const int p = atomicAdd(&g_pos[d], 1);
    g_bin[p] = s;
}

// ---------------- 3) gather aggregation: softmax + weighted sum + tanh ----------------
__global__ void __launch_bounds__(256) aggregate_kernel(float* __restrict__ out,
                                                        const float* __restrict__ bias) {
    const int gw   = (blockIdx.x * blockDim.x + threadIdx.x) >> 5;
    const int lane = threadIdx.x & 31;
    if (gw >= NN) return;
    const int d   = gw;
    const int off = g_off[d];
    const int end = g_off[d + 1];
    const float4 ad4 = *(const float4*)&g_ad[d * HH];

    // pass 1: per-head max
    float4 m = make_float4(-1e30f, -1e30f, -1e30f, -1e30f);
    for (int i = off + lane; i < end; i += 32) {
        const int s = g_bin[i];
        const float4 as4 = *(const float4*)&g_as[s * HH];
        m.x = fmaxf(m.x, lrelu(as4.x + ad4.x));
        m.y = fmaxf(m.y, lrelu(as4.y + ad4.y));
        m.z = fmaxf(m.z, lrelu(as4.z + ad4.z));
        m.w = fmaxf(m.w, lrelu(as4.w + ad4.w));
    }
#pragma unroll
    for (int o = 16; o; o >>= 1) {
        m.x = fmaxf(m.x, __shfl_xor_sync(0xFFFFFFFFu, m.x, o));
        m.y = fmaxf(m.y, __shfl_xor_sync(0xFFFFFFFFu, m.y, o));
        m.z = fmaxf(m.z, __shfl_xor_sync(0xFFFFFFFFu, m.z, o));
        m.w = fmaxf(m.w, __shfl_xor_sync(0xFFFFFFFFu, m.w, o));
    }
    // pass 2: denominators
    float4 den = make_float4(0.f, 0.f, 0.f, 0.f);
    for (int i = off + lane; i < end; i += 32) {
        const int s = g_bin[i];
        const float4 as4 = *(const float4*)&g_as[s * HH];
        den.x += __expf(lrelu(as4.x + ad4.x) - m.x);
        den.y += __expf(lrelu(as4.y + ad4.y) - m.y);
        den.z += __expf(lrelu(as4.z + ad4.z) - m.z);
        den.w += __expf(lrelu(as4.w + ad4.w) - m.w);
    }
#pragma unroll
    for (int o = 16; o; o >>= 1) {
        den.x += __shfl_xor_sync(0xFFFFFFFFu, den.x, o);
        den.y += __shfl_xor_sync(0xFFFFFFFFu, den.y, o);
        den.z += __shfl_xor_sync(0xFFFFFFFFu, den.z, o);
        den.w += __shfl_xor_sync(0xFFFFFFFFu, den.w, o);
    }
    const float4 inv = make_float4(0.25f / den.x, 0.25f / den.y, 0.25f / den.z, 0.25f / den.w);

    // pass 3: weighted feature gather (lane owns 4 channels per head)
    float4 acc = make_float4(0.f, 0.f, 0.f, 0.f);
    const int cb = lane * 4;
    for (int i = off; i < end; i++) {
        const int s = g_bin[i];
        const float4 as4 = *(const float4*)&g_as[s * HH];
        const float w0 = __expf(lrelu(as4.x + ad4.x) - m.x) * inv.x;
        const float w1 = __expf(lrelu(as4.y + ad4.y) - m.y) * inv.y;
        const float w2 = __expf(lrelu(as4.z + ad4.z) - m.z) * inv.z;
        const float w3 = __expf(lrelu(as4.w + ad4.w) - m.w) * inv.w;
        const float* hs = &g_h[(size_t)s * HC];
        const float4 v0 = *(const float4*)&hs[cb];
        const float4 v1 = *(const float4*)&hs[OUTF + cb];
        const float4 v2 = *(const float4*)&hs[2 * OUTF + cb];
        const float4 v3 = *(const float4*)&hs[3 * OUTF + cb];
        acc.x += w0 * v0.x + w1 * v1.x + w2 * v2.x + w3 * v3.x;
        acc.y += w0 * v0.y + w1 * v1.y + w2 * v2.y + w3 * v3.y;
        acc.z += w0 * v0.z + w1 * v1.z + w2 * v2.z + w3 * v3.z;
        acc.w += w0 * v0.w + w1 * v1.w + w2 * v2.w + w3 * v3.w;
    }
    const float4 b4 = *(const float4*)&bias[cb];
    float4 r;
    r.x = tanhf(acc.x + b4.x);
    r.y = tanhf(acc.y + b4.y);
    r.z = tanhf(acc.z + b4.z);
    r.w = tanhf(acc.w + b4.w);
    *(float4*)&out[(size_t)d * OUTF + cb] = r;
}

// ---------------- launch ----------------
extern "C" void kernel_launch(void* const* d_in, const int* in_sizes, int n_in,
                              void* d_out, int out_size) {
    const float* x       = (const float*)d_in[0];
    const int*   eidx    = (const int*)  d_in[1];
    const float* W       = (const float*)d_in[2];
    const float* att_src = (const float*)d_in[3];
    const float* att_dst = (const float*)d_in[4];
    const float* bias    = (const float*)d_in[5];
    float*       out     = (float*)d_out;

    const int* src = eidx;
    const int* dst = eidx + EE;

    prep_kernel<<<(NN * INF_ + 255) / 256, 256>>>(x, W);
    {
        dim3 grid((NN + 127) / 128, HC / 128);   // (235, 4)
        gemm_mma_kernel<<<grid, 256>>>(att_src, att_dst);
    }
    hist_kernel<<<(ET + 255) / 256, 256>>>(dst);
    scan_kernel<<<1, 1024>>>();
    fill_kernel<<<(ET + 255) / 256, 256>>>(src, dst);
    aggregate_kernel<<<(NN + 7) / 8, 256>>>(out, bias);
}

// round 5
// speedup vs baseline: 2.8678x; 1.3369x over previous
#include <cuda_runtime.h>
#include <cuda_bf16.h>
#include <cuda_fp16.h>
#include <cstdint>

// Problem constants
#define NN   30000
#define EE   480000
#define ET   (EE + NN)
#define INF_ 256
#define OUTF 128
#define HH   4
#define HC   (HH * OUTF)      // 512
#define NEG_SLOPE 0.2f
#define NB   ((NN + 511) / 512)   // 59 scan blocks

// ---------------- device scratch ----------------
__device__ __half         g_h[(size_t)NN * HC];        // projected features, fp16 (30.7 MB)
__device__ float          g_as[NN * HH];
__device__ float          g_ad[NN * HH];
__device__ __nv_bfloat16  g_x_hi[(size_t)NN * INF_];
__device__ __nv_bfloat16  g_x_lo[(size_t)NN * INF_];
__device__ __nv_bfloat16  g_Wt_hi[HC * INF_];          // W^T split [512][256]
__device__ __nv_bfloat16  g_Wt_lo[HC * INF_];
__device__ int            g_deg[NN];
__device__ int            g_off[NN + 1];
__device__ int            g_pos[NN];
__device__ int            g_bin[ET];
__device__ int            g_bsum[64];
__device__ int            g_bpre[64];

__device__ __forceinline__ float lrelu(float f) { return f > 0.0f ? f : NEG_SLOPE * f; }

__device__ __forceinline__ uint32_t smem_u32(const void* p) {
    uint32_t a;
    asm("{ .reg .u64 t; cvta.to.shared.u64 t, %1; cvt.u32.u64 %0, t; }" : "=r"(a) : "l"(p));
    return a;
}
__device__ __forceinline__ void ldsm4(uint32_t* r, uint32_t addr) {
    asm volatile("ldmatrix.sync.aligned.m8n8.x4.shared.b16 {%0,%1,%2,%3}, [%4];"
                 : "=r"(r[0]), "=r"(r[1]), "=r"(r[2]), "=r"(r[3]) : "r"(addr));
}
__device__ __forceinline__ void mma_bf16(float* c, const uint32_t* a, const uint32_t* b) {
    asm volatile(
        "mma.sync.aligned.m16n8k16.row.col.f32.bf16.bf16.f32 "
        "{%0,%1,%2,%3}, {%4,%5,%6,%7}, {%8,%9}, {%0,%1,%2,%3};"
        : "+f"(c[0]), "+f"(c[1]), "+f"(c[2]), "+f"(c[3])
        : "r"(a[0]), "r"(a[1]), "r"(a[2]), "r"(a[3]), "r"(b[0]), "r"(b[1]));
}
__device__ __forceinline__ void cp16(uint32_t saddr, const void* gptr) {
    asm volatile("cp.async.ca.shared.global [%0], [%1], 16;"
                 :: "r"(saddr), "l"(gptr));
}
#define CP_COMMIT()  asm volatile("cp.async.commit_group;" ::: "memory")
#define CP_WAIT(n)   asm volatile("cp.async.wait_group %0;" :: "n"(n) : "memory")

// ---------------- 0) prep: split x and W^T into bf16 hi/lo; zero accumulators ----
__global__ void prep_kernel(const float* __restrict__ x, const float* __restrict__ W) {
    const int idx = blockIdx.x * blockDim.x + threadIdx.x;
    if (idx < NN * INF_) {
        const float v = x[idx];
        const __nv_bfloat16 hi = __float2bfloat16_rn(v);
        g_x_hi[idx] = hi;
        g_x_lo[idx] = __float2bfloat16_rn(v - __bfloat162float(hi));
    }
    if (idx < HC * INF_) {
        const int n = idx >> 8;
        const int k = idx & 255;
        const float v = W[(size_t)k * HC + n];
        const __nv_bfloat16 hi = __float2bfloat16_rn(v);
        g_Wt_hi[idx] = hi;
        g_Wt_lo[idx] = __float2bfloat16_rn(v - __bfloat162float(hi));
    }
    if (idx < NN * HH) { g_as[idx] = 0.0f; g_ad[idx] = 0.0f; }
    if (idx < NN) g_deg[idx] = 0;
}

// ---------------- 1) GEMM via mma.sync bf16 (hi/lo split), cp.async 2-stage -------
// Block 128(M) x 128(N)=one head, 8 warps (4x2), warp tile 32x64.
__global__ void __launch_bounds__(256) gemm_mma_kernel(const float* __restrict__ att_src,
                                                       const float* __restrict__ att_dst) {
    __shared__ __align__(16) __nv_bfloat16 As[2][128][40];
    __shared__ __align__(16) __nv_bfloat16 Bs[2][128][40];

    const int tid    = threadIdx.x;
    const int lane   = tid & 31;
    const int wid    = tid >> 5;
    const int warp_m = wid & 3;
    const int warp_n = wid >> 2;
    const int bm     = blockIdx.x * 128;
    const int n0     = blockIdx.y * 128;
    const int head   = blockIdx.y;

    float acc[2][8][4];
#pragma unroll
    for (int i = 0; i < 2; i++)
#pragma unroll
        for (int j = 0; j < 8; j++)
#pragma unroll
            for (int k = 0; k < 4; k++) acc[i][j][k] = 0.0f;

    const uint32_t as_base = smem_u32(&As[0][0][0]);
    const uint32_t bs_base = smem_u32(&Bs[0][0][0]);
    const int a_row = warp_m * 32 + (lane & 15);
    const int a_col = (lane >> 4) * 8;
    const int b_row = warp_n * 64 + (lane & 7) + (lane >> 4) * 8;
    const int b_col = ((lane >> 3) & 1) * 8;

    const __nv_bfloat16* const Asrcs[3] = {g_x_hi, g_x_hi, g_x_lo};
    const __nv_bfloat16* const Bsrcs[3] = {g_Wt_hi, g_Wt_lo, g_Wt_hi};

    const int NITER = 24;   // 3 terms x 8 K-chunks of 32

    auto prefetch = [&](int stage, int it) {
        const int term = it >> 3;
        const int k0   = (it & 7) << 5;
        const __nv_bfloat16* Ap = Asrcs[term];
        const __nv_bfloat16* Bp = Bsrcs[term];
#pragma unroll
        for (int i = 0; i < 2; i++) {
            const int idx = tid + i * 256;
            const int row = idx >> 2;
            const int seg = (idx & 3) * 8;
            const int gr  = bm + row;
            // clamp OOB rows to row 0 (valid memory; results discarded in epilogue)
            const int grc = (gr < NN) ? gr : 0;
            cp16(as_base + (((stage * 128 + row) * 40) + seg) * 2,
                 Ap + (size_t)grc * INF_ + k0 + seg);
            cp16(bs_base + (((stage * 128 + row) * 40) + seg) * 2,
                 Bp + (size_t)(n0 + row) * INF_ + k0 + seg);
        }
        CP_COMMIT();
    };

    prefetch(0, 0);
#pragma unroll 1
    for (int it = 0; it < NITER; it++) {
        const int stage = it & 1;
        if (it + 1 < NITER) {
            prefetch(stage ^ 1, it + 1);
            CP_WAIT(1);
        } else {
            CP_WAIT(0);
        }
        __syncthreads();
#pragma unroll
        for (int ks = 0; ks < 2; ks++) {
            uint32_t af[2][4];
#pragma unroll
            for (int mt = 0; mt < 2; mt++) {
                const uint32_t addr = as_base +
                    ((stage * 128 + a_row + mt * 16) * 40 + ks * 16 + a_col) * 2;
                ldsm4(af[mt], addr);
            }
#pragma unroll
            for (int p = 0; p < 4; p++) {
                uint32_t bf[4];
                const uint32_t addr = bs_base +
                    ((stage * 128 + b_row + p * 16) * 40 + ks * 16 + b_col) * 2;
                ldsm4(bf, addr);
#pragma unroll
                for (int mt = 0; mt < 2; mt++) {
                    mma_bf16(acc[mt][2 * p],     af[mt], bf);
                    mma_bf16(acc[mt][2 * p + 1], af[mt], bf + 2);
                }
            }
        }
        __syncthreads();
    }

    // ---- epilogue: store g_h (fp16), fused attention dot partials ----
    const int r0 = lane >> 2;
    const int cq = (lane & 3) * 2;
    float da[2][2] = {{0.f, 0.f}, {0.f, 0.f}};
    float db[2][2] = {{0.f, 0.f}, {0.f, 0.f}};

#pragma unroll
    for (int mt = 0; mt < 2; mt++) {
        const int gm0 = bm + warp_m * 32 + mt * 16 + r0;
        const int gm1 = gm0 + 8;
#pragma unroll
        for (int nt = 0; nt < 8; nt++) {
            const int cih = warp_n * 64 + nt * 8 + cq;
            const int gc  = n0 + cih;
            const float s0 = att_src[head * OUTF + cih];
            const float s1 = att_src[head * OUTF + cih + 1];
            const float d0 = att_dst[head * OUTF + cih];
            const float d1 = att_dst[head * OUTF + cih + 1];
            const float c0 = acc[mt][nt][0], c1 = acc[mt][nt][1];
            const float c2 = acc[mt][nt][2], c3 = acc[mt][nt][3];
            da[mt][0] += c0 * s0 + c1 * s1;
            db[mt][0] += c0 * d0 + c1 * d1;
            da[mt][1] += c2 * s0 + c3 * s1;
            db[mt][1] += c2 * d0 + c3 * d1;
            if (gm0 < NN)
                *(__half2*)&g_h[(size_t)gm0 * HC + gc] = __floats2half2_rn(c0, c1);
            if (gm1 < NN)
                *(__half2*)&g_h[(size_t)gm1 * HC + gc] = __floats2half2_rn(c2, c3);
        }
    }
#pragma unroll
    for (int mt = 0; mt < 2; mt++)
#pragma unroll
        for (int h = 0; h < 2; h++) {
            da[mt][h] += __shfl_xor_sync(0xFFFFFFFFu, da[mt][h], 1);
            da[mt][h] += __shfl_xor_sync(0xFFFFFFFFu, da[mt][h], 2);
            db[mt][h] += __shfl_xor_sync(0xFFFFFFFFu, db[mt][h], 1);
            db[mt][h] += __shfl_xor_sync(0xFFFFFFFFu, db[mt][h], 2);
        }
    if ((lane & 3) == 0) {
#pragma unroll
        for (int mt = 0; mt < 2; mt++)
#pragma unroll
            for (int h = 0; h < 2; h++) {
                const int gm = bm + warp_m * 32 + mt * 16 + r0 + h * 8;
                if (gm < NN) {
                    atomicAdd(&g_as[gm * HH + head], da[mt][h]);
                    atomicAdd(&g_ad[gm * HH + head], db[mt][h]);
                }
            }
    }
}

// ---------------- 2) CSR build ----------------
__global__ void hist_kernel(const int* __restrict__ dst) {
    const int e = blockIdx.x * blockDim.x + threadIdx.x;
    if (e >= ET) return;
    const int d = (e < EE) ? dst[e] : (e - EE);
    atomicAdd(&g_deg[d], 1);
}

// hierarchical scan: block scans -> top scan -> add back
__global__ void __launch_bounds__(512) scanA_kernel() {
    __shared__ int sm[512];
    const int t = threadIdx.x;
    const int j = blockIdx.x * 512 + t;
    const int v = (j < NN) ? g_deg[j] : 0;
    sm[t] = v;
    __syncthreads();
#pragma unroll
    for (int s = 1; s < 512; s <<= 1) {
        const int u = (t >= s) ? sm[t - s] : 0;
        __syncthreads();
        sm[t] += u;
        __syncthreads();
    }
    if (j < NN) g_off[j] = sm[t] - v;          // local exclusive prefix
    if (t == 511) g_bsum[blockIdx.x] = sm[511];
}

__global__ void __launch_bounds__(64) scanB_kernel() {
    __shared__ int sm[64];
    const int t = threadIdx.x;
    const int v = (t < NB) ? g_bsum[t] : 0;
    sm[t] = v;
    __syncthreads();
#pragma unroll
    for (int s = 1; s < 64; s <<= 1) {
        const int u = (t >= s) ? sm[t - s] : 0;
        __syncthreads();
        sm[t] += u;
        __syncthreads();
    }
    if (t < NB) g_bpre[t] = sm[t] - v;
}

__global__ void __launch_bounds__(512) scanC_kernel() {
    const int j = blockIdx.x * 512 + threadIdx.x;
    if (j < NN) {
        const int o = g_off[j] + g_bpre[blockIdx.x];
        g_off[j] = o;
        g_pos[j] = o;
    }
    if (j == 0) g_off[NN] = ET;
}

__global__ void fill_kernel(const int* __restrict__ src, const int* __restrict__ dst) {
    const int e = blockIdx.x * blockDim.x + threadIdx.x;
    if (e >= ET) return;
    int s, d;
    if (e < EE) { s = src[e]; d = dst[e]; } else { s = d = e - EE; }
    const int p = atomicAdd(&g_pos[d], 1);
    g_bin[p] = s;
}

// ---------------- 3) gather aggregation: softmax + weighted sum + tanh ----------------
__global__ void __launch_bounds__(256) aggregate_kernel(float* __restrict__ out,
                                                        const float* __restrict__ bias) {
    const int gw   = (blockIdx.x * blockDim.x + threadIdx.x) >> 5;
    const int lane = threadIdx.x & 31;
    if (gw >= NN) return;
    const int d   = gw;
    const int off = g_off[d];
    const int end = g_off[d + 1];
    const float4 ad4 = *(const float4*)&g_ad[d * HH];

    // pass 1: per-head max
    float4 m = make_float4(-1e30f, -1e30f, -1e30f, -1e30f);
    for (int i = off + lane; i < end; i += 32) {
        const int s = g_bin[i];
        const float4 as4 = *(const float4*)&g_as[s * HH];
        m.x = fmaxf(m.x, lrelu(as4.x + ad4.x));
        m.y = fmaxf(m.y, lrelu(as4.y + ad4.y));
        m.z = fmaxf(m.z, lrelu(as4.z + ad4.z));
        m.w = fmaxf(m.w, lrelu(as4.w + ad4.w));
    }
#pragma unroll
    for (int o = 16; o; o >>= 1) {
        m.x = fmaxf(m.x, __shfl_xor_sync(0xFFFFFFFFu, m.x, o));
        m.y = fmaxf(m.y, __shfl_xor_sync(0xFFFFFFFFu, m.y, o));
        m.z = fmaxf(m.z, __shfl_xor_sync(0xFFFFFFFFu, m.z, o));
        m.w = fmaxf(m.w, __shfl_xor_sync(0xFFFFFFFFu, m.w, o));
    }
    // pass 2: denominators
    float4 den = make_float4(0.f, 0.f, 0.f, 0.f);
    for (int i = off + lane; i < end; i += 32) {
        const int s = g_bin[i];
        const float4 as4 = *(const float4*)&g_as[s * HH];
        den.x += __expf(lrelu(as4.x + ad4.x) - m.x);
        den.y += __expf(lrelu(as4.y + ad4.y) - m.y);
        den.z += __expf(lrelu(as4.z + ad4.z) - m.z);
        den.w += __expf(lrelu(as4.w + ad4.w) - m.w);
    }
#pragma unroll
    for (int o = 16; o; o >>= 1) {
        den.x += __shfl_xor_sync(0xFFFFFFFFu, den.x, o);
        den.y += __shfl_xor_sync(0xFFFFFFFFu, den.y, o);
        den.z += __shfl_xor_sync(0xFFFFFFFFu, den.z, o);
        den.w += __shfl_xor_sync(0xFFFFFFFFu, den.w, o);
    }
    const float4 inv = make_float4(0.25f / den.x, 0.25f / den.y, 0.25f / den.z, 0.25f / den.w);

    // pass 3: weighted feature gather (fp16 features; lane owns 4 channels per head)
    float4 acc = make_float4(0.f, 0.f, 0.f, 0.f);
    const int cb = lane * 4;
    for (int i = off; i < end; i++) {
        const int s = g_bin[i];
        const float4 as4 = *(const float4*)&g_as[s * HH];
        float w[4];
        w[0] = __expf(lrelu(as4.x + ad4.x) - m.x) * inv.x;
        w[1] = __expf(lrelu(as4.y + ad4.y) - m.y) * inv.y;
        w[2] = __expf(lrelu(as4.z + ad4.z) - m.z) * inv.z;
        w[3] = __expf(lrelu(as4.w + ad4.w) - m.w) * inv.w;
        const __half* hs = &g_h[(size_t)s * HC];
#pragma unroll
        for (int h = 0; h < HH; h++) {
            const uint2 u = *(const uint2*)(hs + h * OUTF + cb);
            const float2 f0 = __half22float2(*(const __half2*)&u.x);
            const float2 f1 = __half22float2(*(const __half2*)&u.y);
            acc.x += w[h] * f0.x;
            acc.y += w[h] * f0.y;
            acc.z += w[h] * f1.x;
            acc.w += w[h] * f1.y;
        }
    }
    const float4 b4 = *(const float4*)&bias[cb];
    float4 r;
    r.x = tanhf(acc.x + b4.x);
    r.y = tanhf(acc.y + b4.y);
    r.z = tanhf(acc.z + b4.z);
    r.w = tanhf(acc.w + b4.w);
    *(float4*)&out[(size_t)d * OUTF + cb] = r;
}

// ---------------- launch ----------------
extern "C" void kernel_launch(void* const* d_in, const int* in_sizes, int n_in,
                              void* d_out, int out_size) {
    const float* x       = (const float*)d_in[0];
    const int*   eidx    = (const int*)  d_in[1];
    const float* W       = (const float*)d_in[2];
    const float* att_src = (const float*)d_in[3];
    const float* att_dst = (const float*)d_in[4];
    const float* bias    = (const float*)d_in[5];
    float*       out     = (float*)d_out;

    const int* src = eidx;
    const int* dst = eidx + EE;

    prep_kernel<<<(NN * INF_ + 255) / 256, 256>>>(x, W);
    {
        dim3 grid((NN + 127) / 128, HC / 128);   // (235, 4)
        gemm_mma_kernel<<<grid, 256>>>(att_src, att_dst);
    }
    hist_kernel<<<(ET + 255) / 256, 256>>>(dst);
    scanA_kernel<<<NB, 512>>>();
    scanB_kernel<<<1, 64>>>();
    scanC_kernel<<<NB, 512>>>();
    fill_kernel<<<(ET + 255) / 256, 256>>>(src, dst);
    aggregate_kernel<<<(NN + 7) / 8, 256>>>(out, bias);
}